// round 5
// baseline (speedup 1.0000x reference)
#include <cuda_runtime.h>

// HamiltonianFlow: 100 RK4 steps, software-pipelined (fwd stage r || bwd stage
// r-1), ONE barrier per region. G-row (f in [SRF,256)) RK4 state lives in SMEM
// and is updated by the reducing lane itself right after the butterfly sum, so
// no intra-region producer->consumer ordering is needed.
//
// W1 transposed in SMEM: wsT[j][f]. Forward: row LDS.128 + fma.rn.f32x2.
// Backward: j in [0,RB) register-cached, j in [RB,256) conflict-free columns.
// G rows backward: L2 LDG at region top + per-lane dots + ILP butterfly.

#define STEPS 100
#define DTV   0.01f
#define SRF   212
#define G     44
#define RB    64
#define NT    256
#define NCTA  128
#define NREG  (4 * STEPS + 1)

typedef unsigned long long ull;

#define WS_FLOATS (256 * SRF)
#define SMEM_FLOATS (WS_FLOATS + 1024 + 1024 + 8 * G)
#define SMEM_BYTES (SMEM_FLOATS * 4)

__device__ __forceinline__ void fma2(ull& d, ull a, ull b) {
    asm("fma.rn.f32x2 %0, %1, %2, %0;" : "+l"(d) : "l"(a), "l"(b));
}
__device__ __forceinline__ ull pk2(float lo, float hi) {
    return (ull)__float_as_uint(lo) | ((ull)__float_as_uint(hi) << 32);
}
__device__ __forceinline__ float psum(ull v) {
    return __uint_as_float((unsigned)(v & 0xffffffffu)) +
           __uint_as_float((unsigned)(v >> 32));
}
__device__ __forceinline__ float dot4(float4 a, float4 b) {
    return a.x * b.x + a.y * b.y + a.z * b.z + a.w * b.w;
}

__global__ __launch_bounds__(NT, 1)
void hflow_kernel(const float* __restrict__ x0,
                  const float* __restrict__ W1,
                  const float* __restrict__ b1,
                  const float* __restrict__ W2,
                  float* __restrict__ out)
{
    extern __shared__ float sm[];
    float* wsT = sm;                        // [256][SRF]
    float* qb  = sm + WS_FLOATS;            // [2 buf][2 samp][256]
    float* ub  = qb + 1024;                 // [2 buf][2 samp][256]
    float* gq0 = ub + 1024;                 // [2][G]
    float* gp0 = gq0 + 2 * G;
    float* gAq = gp0 + 2 * G;
    float* gAp = gAq + 2 * G;

    const int t    = threadIdx.x;
    const int lane = t & 31;
    const int wid  = t >> 5;

    // ---- stage wsT (transposed) ----
    for (int idx = t; idx < SRF * 256; idx += NT) {
        int f = idx / 256, j = idx & 255;
        wsT[j * SRF + f] = W1[f * 256 + j];
    }
    ull wg[G / 2];
#pragma unroll
    for (int k = 0; k < G / 2; k++)
        wg[k] = pk2(W1[(SRF + 2 * k) * 256 + t], W1[(SRF + 2 * k + 1) * 256 + t]);

    const float rb1 = b1[t];
    const float rw2 = W2[t];

    const int s0 = blockIdx.x * 2;
    float2 st0 = ((const float2*)x0)[s0 * 256 + t];
    float2 st1 = ((const float2*)x0)[(s0 + 1) * 256 + t];
    float q0[2], p0[2], Aq[2], Ap[2], pc[2];
    q0[0] = st0.x; p0[0] = st0.y;
    q0[1] = st1.x; p0[1] = st1.y;
    Ap[0] = Ap[1] = 0.f;

    // preload qbuf[0]; init smem-resident state for G rows
    qb[t]       = q0[0];
    qb[256 + t] = q0[1];
    if (t >= SRF) {
        int idx = t - SRF;
        gq0[idx]     = q0[0]; gq0[G + idx] = q0[1];
        gp0[idx]     = p0[0]; gp0[G + idx] = p0[1];
        gAq[idx]     = p0[0]; gAq[G + idx] = p0[1];   // Aq after stage 0 = pc = p0
        gAp[idx]     = 0.f;   gAp[G + idx] = 0.f;
    }
    __syncthreads();

    // register-cache backward j in [0,RB)
    ull rc[RB / 2];
    if (t < SRF) {
#pragma unroll
        for (int k = 0; k < RB / 2; k++)
            rc[k] = pk2(wsT[(2 * k) * SRF + t], wsT[(2 * k + 1) * SRF + t]);
    }

    const float* wrow = wsT + t * SRF;
    const float h2 = 0.5f * DTV;
    const float d6 = DTV / 6.f;
    const int nr = (wid < 4) ? 6 : 5;       // G rows per warp (44 = 8*5 + 4)

    for (int r = 0; r < NREG; r++) {
        const int par = r & 1;
        const float* qc = qb + par * 512;
        float*       qn = qb + (par ^ 1) * 512;
        float*       un = ub + par * 512;
        const float* uc = ub + (par ^ 1) * 512;
        const bool has_f = (r < NREG - 1);
        const bool has_b = (r > 0);
        const int sf = r & 3;
        const float cq = (sf == 2) ? DTV : h2;   // c[sf+1]

        // ---- G-row LDG issue (uc ready at region entry) ----
        float4 wa[6], wb[6];
        if (has_b) {
#pragma unroll
            for (int k = 0; k < 6; k++) {
                if (k < nr) {
                    int row = (k < 5) ? (SRF + wid + 8 * k) : (252 + wid);
                    const float4* wr = (const float4*)(W1 + row * 256);
                    wa[k] = __ldg(&wr[2 * lane]);
                    wb[k] = __ldg(&wr[2 * lane + 1]);
                }
            }
        }

        // ---- forward: z_t = sum_f q_f * wsT[t][f] ----
        if (has_f) {
            ull zA0 = 0, zA1 = 0, zB0 = 0, zB1 = 0;
#pragma unroll 4
            for (int f = 0; f < SRF; f += 4) {
                ulonglong2 w2 = *(const ulonglong2*)&wrow[f];
                ulonglong2 a2 = *(const ulonglong2*)&qc[f];
                ulonglong2 b2 = *(const ulonglong2*)&qc[256 + f];
                fma2(zA0, w2.x, a2.x);
                fma2(zA1, w2.y, a2.y);
                fma2(zB0, w2.x, b2.x);
                fma2(zB1, w2.y, b2.y);
            }
#pragma unroll
            for (int m = 0; m < G / 4; m++) {
                ulonglong2 a2 = *(const ulonglong2*)&qc[SRF + 4 * m];
                ulonglong2 b2 = *(const ulonglong2*)&qc[256 + SRF + 4 * m];
                fma2(zA0, wg[2 * m], a2.x);
                fma2(zA1, wg[2 * m + 1], a2.y);
                fma2(zB0, wg[2 * m], b2.x);
                fma2(zB1, wg[2 * m + 1], b2.y);
            }
            float z0 = psum(zA0) + psum(zA1) + rb1;
            float z1 = psum(zB0) + psum(zB1) + rb1;
            float e0 = __expf(2.f * z0);
            float e1 = __expf(2.f * z1);
            float th0 = 1.f - 2.f / (e0 + 1.f);
            float th1 = 1.f - 2.f / (e1 + 1.f);
            un[t]       = rw2 * (1.f - th0 * th0);
            un[256 + t] = rw2 * (1.f - th1 * th1);
        }

        if (has_b) {
            const int sb = (r - 1) & 3;
            // ---- backward t<SRF: F_t = sum_j wsT[j][t] * u_j ----
            float F[2];
            {
                ull fA0 = 0, fA1 = 0, fB0 = 0, fB1 = 0;
                float Fs0 = 0.f, Fs1 = 0.f;
                if (t < SRF) {
#pragma unroll
                    for (int j = 0; j < RB; j += 4) {
                        ulonglong2 u0 = *(const ulonglong2*)&uc[j];
                        ulonglong2 u1 = *(const ulonglong2*)&uc[256 + j];
                        int k = j >> 1;
                        fma2(fA0, rc[k], u0.x);
                        fma2(fA1, rc[k + 1], u0.y);
                        fma2(fB0, rc[k], u1.x);
                        fma2(fB1, rc[k + 1], u1.y);
                    }
#pragma unroll 6
                    for (int j = RB; j < 256; j += 4) {
                        float4 u0 = *(const float4*)&uc[j];
                        float4 u1 = *(const float4*)&uc[256 + j];
                        float w0 = wsT[(j + 0) * SRF + t];
                        float w1 = wsT[(j + 1) * SRF + t];
                        float w2 = wsT[(j + 2) * SRF + t];
                        float w3 = wsT[(j + 3) * SRF + t];
                        Fs0 += w0 * u0.x + w1 * u0.y + w2 * u0.z + w3 * u0.w;
                        Fs1 += w0 * u1.x + w1 * u1.y + w2 * u1.z + w3 * u1.w;
                    }
                }
                F[0] = psum(fA0) + psum(fA1) + Fs0;
                F[1] = psum(fB0) + psum(fB1) + Fs1;
            }
            // ---- G rows: dots + butterfly; reducing lane updates smem state ----
            {
                float4 ua0 = *(const float4*)&uc[8 * lane];
                float4 ua1 = *(const float4*)&uc[8 * lane + 4];
                float4 ubx = *(const float4*)&uc[256 + 8 * lane];
                float4 uby = *(const float4*)&uc[256 + 8 * lane + 4];
                float v0[6], v1[6];
#pragma unroll
                for (int k = 0; k < 6; k++) {
                    if (k < nr) {
                        v0[k] = dot4(wa[k], ua0) + dot4(wb[k], ua1);
                        v1[k] = dot4(wa[k], ubx) + dot4(wb[k], uby);
                    }
                }
#pragma unroll
                for (int m = 16; m >= 1; m >>= 1) {
#pragma unroll
                    for (int k = 0; k < 6; k++) {
                        if (k < nr) {
                            v0[k] += __shfl_xor_sync(0xffffffffu, v0[k], m);
                            v1[k] += __shfl_xor_sync(0xffffffffu, v1[k], m);
                        }
                    }
                }
                if (lane < nr) {
                    float Fg0 = v0[0], Fg1 = v1[0];
#pragma unroll
                    for (int k = 1; k < 6; k++)
                        if (lane == k) { Fg0 = v0[k]; Fg1 = v1[k]; }
                    int row = (lane < 5) ? (SRF + wid + 8 * lane) : (252 + wid);
                    int idx = row - SRF;
#pragma unroll
                    for (int m = 0; m < 2; m++) {
                        float Fg  = (m == 0) ? Fg0 : Fg1;
                        float qg  = gq0[m * G + idx];
                        float pg  = gp0[m * G + idx];
                        float Aqg = gAq[m * G + idx];
                        float Apg = gAp[m * G + idx];
                        float pcg;
                        if (sb == 3) {
                            Apg += Fg;
                            pg  -= d6 * Apg;
                            Apg  = 0.f;
                            pcg  = pg;
                            Aqg  = pcg;
                        } else {
                            const float wb_ = (sb == 0) ? 1.f : 2.f;
                            const float cn  = (sb == 2) ? DTV : h2;
                            const float wn  = (sb == 2) ? 1.f : 2.f;
                            Apg += wb_ * Fg;
                            pcg  = pg - cn * Fg;
                            Aqg += wn * pcg;
                        }
                        if (has_f) {
                            if (sf == 3) {
                                qg += d6 * Aqg;
                                qn[m * 256 + row] = qg;
                            } else {
                                qn[m * 256 + row] = qg + cq * pcg;
                            }
                        }
                        gq0[m * G + idx] = qg;
                        gp0[m * G + idx] = pg;
                        gAq[m * G + idx] = Aqg;
                        gAp[m * G + idx] = Apg;
                    }
                }
            }
            // ---- state update for own row (t < SRF) ----
            if (t < SRF) {
                if (sb == 3) {
#pragma unroll
                    for (int m = 0; m < 2; m++) {
                        Ap[m] += F[m];
                        p0[m] -= d6 * Ap[m];
                        Ap[m] = 0.f;
                        pc[m] = p0[m];
                        Aq[m] = pc[m];
                    }
                } else {
                    const float wb_ = (sb == 0) ? 1.f : 2.f;
                    const float cn  = (sb == 2) ? DTV : h2;
                    const float wn  = (sb == 2) ? 1.f : 2.f;
#pragma unroll
                    for (int m = 0; m < 2; m++) {
                        Ap[m] += wb_ * F[m];
                        pc[m] = p0[m] - cn * F[m];
                        Aq[m] += wn * pc[m];
                    }
                }
                if (has_f) {
                    if (sf == 3) {
                        q0[0] += d6 * Aq[0];
                        q0[1] += d6 * Aq[1];
                        qn[t]       = q0[0];
                        qn[256 + t] = q0[1];
                    } else {
                        qn[t]       = q0[0] + cq * pc[0];
                        qn[256 + t] = q0[1] + cq * pc[1];
                    }
                }
            }
        } else {
            // r == 0: stage 0 for ALL threads (incl. t >= SRF)
            pc[0] = p0[0]; Aq[0] = pc[0];
            pc[1] = p0[1]; Aq[1] = pc[1];
            qn[t]       = q0[0] + cq * pc[0];
            qn[256 + t] = q0[1] + cq * pc[1];
        }

        __syncthreads();                    // single barrier per region
    }

    if (t >= SRF) {
        int idx = t - SRF;
        q0[0] = gq0[idx];     p0[0] = gp0[idx];
        q0[1] = gq0[G + idx]; p0[1] = gp0[G + idx];
    }
    ((float2*)out)[s0 * 256 + t]       = make_float2(q0[0], p0[0]);
    ((float2*)out)[(s0 + 1) * 256 + t] = make_float2(q0[1], p0[1]);
}

extern "C" void kernel_launch(void* const* d_in, const int* in_sizes, int n_in,
                              void* d_out, int out_size) {
    const float* x0 = (const float*)d_in[0];
    const float* W1 = (const float*)d_in[1];
    const float* b1 = (const float*)d_in[2];
    const float* W2 = (const float*)d_in[3];
    cudaFuncSetAttribute(hflow_kernel,
                         cudaFuncAttributeMaxDynamicSharedMemorySize, SMEM_BYTES);
    hflow_kernel<<<NCTA, NT, SMEM_BYTES>>>(x0, W1, b1, W2, (float*)d_out);
}

// round 6
// speedup vs baseline: 1.0010x; 1.0010x over previous
#include <cuda_runtime.h>

// HamiltonianFlow: 100 RK4 steps, software-pipelined (fwd stage r || bwd stage
// r-1), ONE barrier per region. G-row (f in [SRF,256)) RK4 state lives in SMEM
// and is updated by the reducing lane itself right after the butterfly sum, so
// no intra-region producer->consumer ordering is needed.
//
// W1 transposed in SMEM: wsT[j][f]. Forward: row LDS.128 + fma.rn.f32x2.
// Backward: j in [0,RB) register-cached, j in [RB,256) conflict-free columns.
// G rows backward: L2 LDG at region top + per-lane dots + ILP butterfly.

#define STEPS 100
#define DTV   0.01f
#define SRF   212
#define G     44
#define RB    64
#define NT    256
#define NCTA  128
#define NREG  (4 * STEPS + 1)

typedef unsigned long long ull;

#define WS_FLOATS (256 * SRF)
#define SMEM_FLOATS (WS_FLOATS + 1024 + 1024 + 8 * G)
#define SMEM_BYTES (SMEM_FLOATS * 4)

__device__ __forceinline__ void fma2(ull& d, ull a, ull b) {
    asm("fma.rn.f32x2 %0, %1, %2, %0;" : "+l"(d) : "l"(a), "l"(b));
}
__device__ __forceinline__ ull pk2(float lo, float hi) {
    return (ull)__float_as_uint(lo) | ((ull)__float_as_uint(hi) << 32);
}
__device__ __forceinline__ float psum(ull v) {
    return __uint_as_float((unsigned)(v & 0xffffffffu)) +
           __uint_as_float((unsigned)(v >> 32));
}
__device__ __forceinline__ float dot4(float4 a, float4 b) {
    return a.x * b.x + a.y * b.y + a.z * b.z + a.w * b.w;
}

__global__ __launch_bounds__(NT, 1)
void hflow_kernel(const float* __restrict__ x0,
                  const float* __restrict__ W1,
                  const float* __restrict__ b1,
                  const float* __restrict__ W2,
                  float* __restrict__ out)
{
    extern __shared__ float sm[];
    float* wsT = sm;                        // [256][SRF]
    float* qb  = sm + WS_FLOATS;            // [2 buf][2 samp][256]
    float* ub  = qb + 1024;                 // [2 buf][2 samp][256]
    float* gq0 = ub + 1024;                 // [2][G]
    float* gp0 = gq0 + 2 * G;
    float* gAq = gp0 + 2 * G;
    float* gAp = gAq + 2 * G;

    const int t    = threadIdx.x;
    const int lane = t & 31;
    const int wid  = t >> 5;

    // ---- stage wsT (transposed) ----
    for (int idx = t; idx < SRF * 256; idx += NT) {
        int f = idx / 256, j = idx & 255;
        wsT[j * SRF + f] = W1[f * 256 + j];
    }
    ull wg[G / 2];
#pragma unroll
    for (int k = 0; k < G / 2; k++)
        wg[k] = pk2(W1[(SRF + 2 * k) * 256 + t], W1[(SRF + 2 * k + 1) * 256 + t]);

    const float rb1 = b1[t];
    const float rw2 = W2[t];

    const int s0 = blockIdx.x * 2;
    float2 st0 = ((const float2*)x0)[s0 * 256 + t];
    float2 st1 = ((const float2*)x0)[(s0 + 1) * 256 + t];
    float q0[2], p0[2], Aq[2], Ap[2], pc[2];
    q0[0] = st0.x; p0[0] = st0.y;
    q0[1] = st1.x; p0[1] = st1.y;
    Ap[0] = Ap[1] = 0.f;

    // preload qbuf[0]; init smem-resident state for G rows
    qb[t]       = q0[0];
    qb[256 + t] = q0[1];
    if (t >= SRF) {
        int idx = t - SRF;
        gq0[idx]     = q0[0]; gq0[G + idx] = q0[1];
        gp0[idx]     = p0[0]; gp0[G + idx] = p0[1];
        gAq[idx]     = p0[0]; gAq[G + idx] = p0[1];   // Aq after stage 0 = pc = p0
        gAp[idx]     = 0.f;   gAp[G + idx] = 0.f;
    }
    __syncthreads();

    // register-cache backward j in [0,RB)
    ull rc[RB / 2];
    if (t < SRF) {
#pragma unroll
        for (int k = 0; k < RB / 2; k++)
            rc[k] = pk2(wsT[(2 * k) * SRF + t], wsT[(2 * k + 1) * SRF + t]);
    }

    const float* wrow = wsT + t * SRF;
    const float h2 = 0.5f * DTV;
    const float d6 = DTV / 6.f;
    const int nr = (wid < 4) ? 6 : 5;       // G rows per warp (44 = 8*5 + 4)

    for (int r = 0; r < NREG; r++) {
        const int par = r & 1;
        const float* qc = qb + par * 512;
        float*       qn = qb + (par ^ 1) * 512;
        float*       un = ub + par * 512;
        const float* uc = ub + (par ^ 1) * 512;
        const bool has_f = (r < NREG - 1);
        const bool has_b = (r > 0);
        const int sf = r & 3;
        const float cq = (sf == 2) ? DTV : h2;   // c[sf+1]

        // ---- G-row LDG issue (uc ready at region entry) ----
        float4 wa[6], wb[6];
        if (has_b) {
#pragma unroll
            for (int k = 0; k < 6; k++) {
                if (k < nr) {
                    int row = (k < 5) ? (SRF + wid + 8 * k) : (252 + wid);
                    const float4* wr = (const float4*)(W1 + row * 256);
                    wa[k] = __ldg(&wr[2 * lane]);
                    wb[k] = __ldg(&wr[2 * lane + 1]);
                }
            }
        }

        // ---- forward: z_t = sum_f q_f * wsT[t][f] ----
        if (has_f) {
            ull zA0 = 0, zA1 = 0, zB0 = 0, zB1 = 0;
#pragma unroll 4
            for (int f = 0; f < SRF; f += 4) {
                ulonglong2 w2 = *(const ulonglong2*)&wrow[f];
                ulonglong2 a2 = *(const ulonglong2*)&qc[f];
                ulonglong2 b2 = *(const ulonglong2*)&qc[256 + f];
                fma2(zA0, w2.x, a2.x);
                fma2(zA1, w2.y, a2.y);
                fma2(zB0, w2.x, b2.x);
                fma2(zB1, w2.y, b2.y);
            }
#pragma unroll
            for (int m = 0; m < G / 4; m++) {
                ulonglong2 a2 = *(const ulonglong2*)&qc[SRF + 4 * m];
                ulonglong2 b2 = *(const ulonglong2*)&qc[256 + SRF + 4 * m];
                fma2(zA0, wg[2 * m], a2.x);
                fma2(zA1, wg[2 * m + 1], a2.y);
                fma2(zB0, wg[2 * m], b2.x);
                fma2(zB1, wg[2 * m + 1], b2.y);
            }
            float z0 = psum(zA0) + psum(zA1) + rb1;
            float z1 = psum(zB0) + psum(zB1) + rb1;
            float e0 = __expf(2.f * z0);
            float e1 = __expf(2.f * z1);
            float th0 = 1.f - 2.f / (e0 + 1.f);
            float th1 = 1.f - 2.f / (e1 + 1.f);
            un[t]       = rw2 * (1.f - th0 * th0);
            un[256 + t] = rw2 * (1.f - th1 * th1);
        }

        if (has_b) {
            const int sb = (r - 1) & 3;
            // ---- backward t<SRF: F_t = sum_j wsT[j][t] * u_j ----
            float F[2];
            {
                ull fA0 = 0, fA1 = 0, fB0 = 0, fB1 = 0;
                float Fs0 = 0.f, Fs1 = 0.f;
                if (t < SRF) {
#pragma unroll
                    for (int j = 0; j < RB; j += 4) {
                        ulonglong2 u0 = *(const ulonglong2*)&uc[j];
                        ulonglong2 u1 = *(const ulonglong2*)&uc[256 + j];
                        int k = j >> 1;
                        fma2(fA0, rc[k], u0.x);
                        fma2(fA1, rc[k + 1], u0.y);
                        fma2(fB0, rc[k], u1.x);
                        fma2(fB1, rc[k + 1], u1.y);
                    }
#pragma unroll 6
                    for (int j = RB; j < 256; j += 4) {
                        float4 u0 = *(const float4*)&uc[j];
                        float4 u1 = *(const float4*)&uc[256 + j];
                        float w0 = wsT[(j + 0) * SRF + t];
                        float w1 = wsT[(j + 1) * SRF + t];
                        float w2 = wsT[(j + 2) * SRF + t];
                        float w3 = wsT[(j + 3) * SRF + t];
                        Fs0 += w0 * u0.x + w1 * u0.y + w2 * u0.z + w3 * u0.w;
                        Fs1 += w0 * u1.x + w1 * u1.y + w2 * u1.z + w3 * u1.w;
                    }
                }
                F[0] = psum(fA0) + psum(fA1) + Fs0;
                F[1] = psum(fB0) + psum(fB1) + Fs1;
            }
            // ---- G rows: dots + butterfly; reducing lane updates smem state ----
            {
                float4 ua0 = *(const float4*)&uc[8 * lane];
                float4 ua1 = *(const float4*)&uc[8 * lane + 4];
                float4 ubx = *(const float4*)&uc[256 + 8 * lane];
                float4 uby = *(const float4*)&uc[256 + 8 * lane + 4];
                float v0[6], v1[6];
#pragma unroll
                for (int k = 0; k < 6; k++) {
                    if (k < nr) {
                        v0[k] = dot4(wa[k], ua0) + dot4(wb[k], ua1);
                        v1[k] = dot4(wa[k], ubx) + dot4(wb[k], uby);
                    }
                }
#pragma unroll
                for (int m = 16; m >= 1; m >>= 1) {
#pragma unroll
                    for (int k = 0; k < 6; k++) {
                        if (k < nr) {
                            v0[k] += __shfl_xor_sync(0xffffffffu, v0[k], m);
                            v1[k] += __shfl_xor_sync(0xffffffffu, v1[k], m);
                        }
                    }
                }
                if (lane < nr) {
                    float Fg0 = v0[0], Fg1 = v1[0];
#pragma unroll
                    for (int k = 1; k < 6; k++)
                        if (lane == k) { Fg0 = v0[k]; Fg1 = v1[k]; }
                    int row = (lane < 5) ? (SRF + wid + 8 * lane) : (252 + wid);
                    int idx = row - SRF;
#pragma unroll
                    for (int m = 0; m < 2; m++) {
                        float Fg  = (m == 0) ? Fg0 : Fg1;
                        float qg  = gq0[m * G + idx];
                        float pg  = gp0[m * G + idx];
                        float Aqg = gAq[m * G + idx];
                        float Apg = gAp[m * G + idx];
                        float pcg;
                        if (sb == 3) {
                            Apg += Fg;
                            pg  -= d6 * Apg;
                            Apg  = 0.f;
                            pcg  = pg;
                            Aqg  = pcg;
                        } else {
                            const float wb_ = (sb == 0) ? 1.f : 2.f;
                            const float cn  = (sb == 2) ? DTV : h2;
                            const float wn  = (sb == 2) ? 1.f : 2.f;
                            Apg += wb_ * Fg;
                            pcg  = pg - cn * Fg;
                            Aqg += wn * pcg;
                        }
                        if (has_f) {
                            if (sf == 3) {
                                qg += d6 * Aqg;
                                qn[m * 256 + row] = qg;
                            } else {
                                qn[m * 256 + row] = qg + cq * pcg;
                            }
                        }
                        gq0[m * G + idx] = qg;
                        gp0[m * G + idx] = pg;
                        gAq[m * G + idx] = Aqg;
                        gAp[m * G + idx] = Apg;
                    }
                }
            }
            // ---- state update for own row (t < SRF) ----
            if (t < SRF) {
                if (sb == 3) {
#pragma unroll
                    for (int m = 0; m < 2; m++) {
                        Ap[m] += F[m];
                        p0[m] -= d6 * Ap[m];
                        Ap[m] = 0.f;
                        pc[m] = p0[m];
                        Aq[m] = pc[m];
                    }
                } else {
                    const float wb_ = (sb == 0) ? 1.f : 2.f;
                    const float cn  = (sb == 2) ? DTV : h2;
                    const float wn  = (sb == 2) ? 1.f : 2.f;
#pragma unroll
                    for (int m = 0; m < 2; m++) {
                        Ap[m] += wb_ * F[m];
                        pc[m] = p0[m] - cn * F[m];
                        Aq[m] += wn * pc[m];
                    }
                }
                if (has_f) {
                    if (sf == 3) {
                        q0[0] += d6 * Aq[0];
                        q0[1] += d6 * Aq[1];
                        qn[t]       = q0[0];
                        qn[256 + t] = q0[1];
                    } else {
                        qn[t]       = q0[0] + cq * pc[0];
                        qn[256 + t] = q0[1] + cq * pc[1];
                    }
                }
            }
        } else {
            // r == 0: stage 0 for ALL threads (incl. t >= SRF)
            pc[0] = p0[0]; Aq[0] = pc[0];
            pc[1] = p0[1]; Aq[1] = pc[1];
            qn[t]       = q0[0] + cq * pc[0];
            qn[256 + t] = q0[1] + cq * pc[1];
        }

        __syncthreads();                    // single barrier per region
    }

    if (t >= SRF) {
        int idx = t - SRF;
        q0[0] = gq0[idx];     p0[0] = gp0[idx];
        q0[1] = gq0[G + idx]; p0[1] = gp0[G + idx];
    }
    ((float2*)out)[s0 * 256 + t]       = make_float2(q0[0], p0[0]);
    ((float2*)out)[(s0 + 1) * 256 + t] = make_float2(q0[1], p0[1]);
}

extern "C" void kernel_launch(void* const* d_in, const int* in_sizes, int n_in,
                              void* d_out, int out_size) {
    const float* x0 = (const float*)d_in[0];
    const float* W1 = (const float*)d_in[1];
    const float* b1 = (const float*)d_in[2];
    const float* W2 = (const float*)d_in[3];
    cudaFuncSetAttribute(hflow_kernel,
                         cudaFuncAttributeMaxDynamicSharedMemorySize, SMEM_BYTES);
    hflow_kernel<<<NCTA, NT, SMEM_BYTES>>>(x0, W1, b1, W2, (float*)d_out);
}